// round 1
// baseline (speedup 1.0000x reference)
#include <cuda_runtime.h>

// Problem constants (fixed by the reference):
//   B=8192, A=26, NUM_TYPES=3, ANCHOR_DIM=31 (20 anchors, 10 vis, 1 class)
//   total "triples" (b,a,type) = 8192*26*3 = 638976, each 31 contiguous floats.
#define ANCHOR_DIM 31
#define KSTEPS 10
#define EPSF 1e-9f

constexpr int TRIPLES_PER_BLOCK = 128;
constexpr int THREADS = 128;
constexpr int FLOATS_PER_BLOCK = TRIPLES_PER_BLOCK * ANCHOR_DIM;  // 3968
constexpr int VEC_PER_BLOCK = FLOATS_PER_BLOCK / 4;               // 992 float4s

__device__ double g_acc[3];  // raw sums: S0 (vis bce), S1 (class bce), S2 (abs)

// Fast fp32 natural log (cephes-style). Valid for x in (0, 2]; rel err ~1e-7.
// Avoids MUFU (rt=8/SMSP would make 14M logs the bottleneck) — pure FMA pipe.
__device__ __forceinline__ float flogf(float x) {
    int ix = __float_as_int(x);
    float e = (float)((ix >> 23) - 126);
    float m = __int_as_float((ix & 0x007FFFFF) | 0x3F000000);  // [0.5, 1)
    if (m < 0.70710678118f) { m = m + m; e -= 1.0f; }          // m in [~0.707, ~1.414)
    float t = m - 1.0f;
    float z = t * t;
    float y = 7.0376836292e-2f;
    y = y * t - 1.1514610310e-1f;
    y = y * t + 1.1676998740e-1f;
    y = y * t - 1.2420140846e-1f;
    y = y * t + 1.4249322787e-1f;
    y = y * t - 1.6668057665e-1f;
    y = y * t + 2.0000714765e-1f;
    y = y * t - 2.4999993993e-1f;
    y = y * t + 3.3333331174e-1f;
    y = y * t * z;
    y = y - 0.5f * z;
    return t + y + e * 0.69314718055994531f;
}

__global__ void init_acc_kernel() {
    g_acc[0] = 0.0; g_acc[1] = 0.0; g_acc[2] = 0.0;
}

__global__ void __launch_bounds__(THREADS)
loss_kernel(const float* __restrict__ pred, const float* __restrict__ gt) {
    __shared__ float sp[FLOATS_PER_BLOCK];
    __shared__ float sg[FLOATS_PER_BLOCK];

    // Stage this block's contiguous chunk with float4 LDGs (LSU-issue friendly).
    size_t base = (size_t)blockIdx.x * FLOATS_PER_BLOCK;
    const float4* p4 = reinterpret_cast<const float4*>(pred + base);
    const float4* g4 = reinterpret_cast<const float4*>(gt + base);
    float4* sp4 = reinterpret_cast<float4*>(sp);
    float4* sg4 = reinterpret_cast<float4*>(sg);
#pragma unroll 4
    for (int i = threadIdx.x; i < VEC_PER_BLOCK; i += THREADS) {
        sp4[i] = p4[i];
        sg4[i] = g4[i];
    }
    __syncthreads();

    // One triple per thread. SMEM stride 31 is coprime with 32 banks -> conflict-free.
    const float* tp = sp + threadIdx.x * ANCHOR_DIM;
    const float* tg = sg + threadIdx.x * ANCHOR_DIM;

    float s0 = 0.0f, s2 = 0.0f;
    float gvis[KSTEPS];
#pragma unroll
    for (int j = 0; j < KSTEPS; j++) {
        float g = tg[2 * KSTEPS + j];
        float p = tp[2 * KSTEPS + j];
        gvis[j] = g;
        s0 += g * flogf(p + EPSF) + (1.0f - g + EPSF) * flogf(1.0f - p + EPSF);
    }
    float gcls = tg[3 * KSTEPS];
    float pcls = tp[3 * KSTEPS];
    float s1 = gcls * flogf(pcls + EPSF) + (1.0f - gcls) * flogf(1.0f - pcls + EPSF);
#pragma unroll
    for (int j = 0; j < 2 * KSTEPS; j++) {
        s2 += fabsf(gcls * gvis[j % KSTEPS] * (tp[j] - tg[j]));
    }

    // Warp reduce (3 values, 5 butterfly steps each).
#pragma unroll
    for (int o = 16; o > 0; o >>= 1) {
        s0 += __shfl_xor_sync(0xffffffffu, s0, o);
        s1 += __shfl_xor_sync(0xffffffffu, s1, o);
        s2 += __shfl_xor_sync(0xffffffffu, s2, o);
    }

    __shared__ float red[3][THREADS / 32];
    int wid = threadIdx.x >> 5;
    int lid = threadIdx.x & 31;
    if (lid == 0) { red[0][wid] = s0; red[1][wid] = s1; red[2][wid] = s2; }
    __syncthreads();
    if (threadIdx.x == 0) {
        float a0 = 0.0f, a1 = 0.0f, a2 = 0.0f;
#pragma unroll
        for (int w = 0; w < THREADS / 32; w++) { a0 += red[0][w]; a1 += red[1][w]; a2 += red[2][w]; }
        atomicAdd(&g_acc[0], (double)a0);
        atomicAdd(&g_acc[1], (double)a1);
        atomicAdd(&g_acc[2], (double)a2);
    }
}

__global__ void finalize_kernel(float* __restrict__ out) {
    float l0 = (float)(-g_acc[0] / (double)KSTEPS);
    float l1 = (float)(-g_acc[1]);
    float l2 = (float)(g_acc[2]);
    out[0] = l0 + l1 + l2;
    out[1] = l0;
    out[2] = l1;
    out[3] = l2;
}

extern "C" void kernel_launch(void* const* d_in, const int* in_sizes, int n_in,
                              void* d_out, int out_size) {
    const float* pred = (const float*)d_in[0];
    const float* gt   = (const float*)d_in[1];
    // d_in[2..5] (hcam/pitch) are unused by the reference.

    int total_floats = in_sizes[0];                 // 8192*26*93 = 19,808,256
    int triples = total_floats / ANCHOR_DIM;        // 638,976
    int blocks = triples / TRIPLES_PER_BLOCK;       // 4,992 (exact)

    init_acc_kernel<<<1, 1>>>();
    loss_kernel<<<blocks, THREADS>>>(pred, gt);
    finalize_kernel<<<1, 1>>>((float*)d_out);
}